// round 9
// baseline (speedup 1.0000x reference)
#include <cuda_runtime.h>
#include <cstdint>

#define DD 8
#define BB 8
#define NN 2048
#define NN2 (NN * NN)        // 4194304
#define NQ  (NN2 / 4)        // 1048576 quads (4 o's per quad)

// Gate byte per synapse (e,o): bit b set iff Xd[didx(e,o), b, e]==1. Packed 4/word.
__device__ unsigned int g_gate[NQ];   // 4 MB static scratch

// ---------------------------------------------------------------------------
// Kernel 1: gate kernel with in-CTA spike pack + active-plane skipping.
//   One CTA per e-row (512 quads); each thread handles 2 quads.
//   Only delay planes with >=1 spike (any batch) are read: ~2.7/8 planes,
//   cutting delaymap traffic 134 MB -> ~45 MB. One-hot => gate byte = m8(d).
// ---------------------------------------------------------------------------
__global__ void __launch_bounds__(256)
gate_kernel(const float4* __restrict__ dm4, const float* __restrict__ Xd) {
    const int e  = blockIdx.x;                        // one e per CTA
    const int i0 = e * 512 + threadIdx.x;             // first quad
    const int i1 = i0 + 256;                          // second quad

    __shared__ unsigned sm_bits[2];
    if (threadIdx.x < 64) {
        const bool sp = Xd[(size_t)threadIdx.x * NN + e] > 0.5f;
        const unsigned bal = __ballot_sync(0xFFFFFFFFu, sp);
        if ((threadIdx.x & 31) == 0) sm_bits[threadIdx.x >> 5] = bal;
    }
    __syncthreads();
    const unsigned long long bits =
        (unsigned long long)sm_bits[0] | ((unsigned long long)sm_bits[1] << 32);

    unsigned a0 = 0, a1 = 0, a2 = 0, a3 = 0;   // gate bytes, quad 0
    unsigned b0 = 0, b1 = 0, b2 = 0, b3 = 0;   // gate bytes, quad 1
#pragma unroll
    for (int d = 0; d < DD; d++) {
        const unsigned m8 = (unsigned)(bits >> (d * 8)) & 0xFFu;
        if (m8) {                                     // CTA-uniform branch
            const float4 u = dm4[(size_t)d * NQ + i0];
            const float4 v = dm4[(size_t)d * NQ + i1];
            if (u.x > 0.5f) a0 = m8;
            if (u.y > 0.5f) a1 = m8;
            if (u.z > 0.5f) a2 = m8;
            if (u.w > 0.5f) a3 = m8;
            if (v.x > 0.5f) b0 = m8;
            if (v.y > 0.5f) b1 = m8;
            if (v.z > 0.5f) b2 = m8;
            if (v.w > 0.5f) b3 = m8;
        }
    }
    g_gate[i0] = a0 | (a1 << 8) | (a2 << 16) | (a3 << 24);
    g_gate[i1] = b0 | (b1 << 8) | (b2 << 16) | (b3 << 24);
}

// ---------------------------------------------------------------------------
// Kernel 2: gated blend + reduce, thread -> (o-quad, batch).
//   Block = 8 warps; warp w = batch b over the SAME 128 o (32 lanes x 4 o).
//   Per warp-iter: 1 gate LDG.32 + 3 static LDG.128 + 1 predicated Wlong
//   LDG.128 = 5 LDG per 128 cells (4x fewer LDG instructions than R8).
//   4 accumulators/thread; single skip branch on the whole gate word.
// ---------------------------------------------------------------------------
#define ESPLIT 128
#define ECHUNK (NN / ESPLIT)   // 16

__global__ void __launch_bounds__(256)
reduce_kernel(const float4* __restrict__ W4,    // (N,N)
              const float4* __restrict__ Wl4,   // Wlong (B,N,N)
              const float4* __restrict__ F4,    // STDP_frac (N,N)
              const float4* __restrict__ S4,    // signs (N,N)
              float* __restrict__ out)          // (B,N)
{
    const int lane = threadIdx.x & 31;
    const int b    = threadIdx.x >> 5;               // warp index = batch
    const int q    = blockIdx.x * 32 + lane;         // quad index in row (0..511)
    const int o    = q * 4;
    const int ebase = blockIdx.y * ECHUNK;
    const float4* __restrict__ wlb = Wl4 + (size_t)b * (NN2 / 4);

    float a0 = 0.f, a1 = 0.f, a2 = 0.f, a3 = 0.f;
    size_t idx = (size_t)ebase * (NN / 4) + q;       // float4/uint index

#pragma unroll 4
    for (int ee = 0; ee < ECHUNK; ee++, idx += (NN / 4)) {
        const unsigned g = g_gate[idx];
        if (g == 0) continue;                        // no batch on at any of 4 o

        // Union of gate bits over the 4 o's: predicate for the Wlong vector load
        const unsigned un = g | (g >> 8) | (g >> 16) | (g >> 24);
        const bool on = (un >> b) & 1u;

        const float4 s = S4[idx];
        const float4 w = W4[idx];
        const float4 f = F4[idx];
        float4 wl = make_float4(0.f, 0.f, 0.f, 0.f);
        if (on) wl = wlb[idx];                       // @P LDG.128

        // s * (w*(1-f) + f*wl) = s * fma(f, wl - w, w)
        if ((g >>  b)       & 1u) a0 += s.x * fmaf(f.x, wl.x - w.x, w.x);
        if ((g >> ( 8 + b)) & 1u) a1 += s.y * fmaf(f.y, wl.y - w.y, w.y);
        if ((g >> (16 + b)) & 1u) a2 += s.z * fmaf(f.z, wl.z - w.z, w.z);
        if ((g >> (24 + b)) & 1u) a3 += s.w * fmaf(f.w, wl.w - w.w, w.w);
    }

    float* op = out + b * NN + o;
    atomicAdd(op + 0, a0);
    atomicAdd(op + 1, a1);
    atomicAdd(op + 2, a2);
    atomicAdd(op + 3, a3);
}

// ---------------------------------------------------------------------------
// Launch
// ---------------------------------------------------------------------------
extern "C" void kernel_launch(void* const* d_in, const int* in_sizes, int n_in,
                              void* d_out, int out_size) {
    const float* Xd = (const float*)d_in[0];   // (D,B,N)
    const float* dm = (const float*)d_in[1];   // (D,N,N)
    const float* W  = (const float*)d_in[2];   // (N,N)
    const float* Wl = (const float*)d_in[3];   // (B,N,N)
    const float* F  = (const float*)d_in[4];   // (N,N)
    const float* S  = (const float*)d_in[5];   // (N,N)
    float* out = (float*)d_out;                // (B,N)

    cudaMemsetAsync(out, 0, BB * NN * sizeof(float));

    gate_kernel<<<NN, 256>>>((const float4*)dm, Xd);

    dim3 grid((NN / 4) / 32, ESPLIT);   // 16 x 128 = 2048 CTAs
    reduce_kernel<<<grid, 256>>>((const float4*)W, (const float4*)Wl,
                                 (const float4*)F, (const float4*)S, out);
}

// round 10
// speedup vs baseline: 1.7403x; 1.7403x over previous
#include <cuda_runtime.h>
#include <cstdint>

#define DD 8
#define BB 8
#define NN 2048
#define NN2 (NN * NN)        // 4194304
#define NQ  (NN2 / 4)        // 1048576 quads (4 o's per quad)

// Gate byte per synapse (e,o): bit b set iff Xd[didx(e,o), b, e]==1. Packed 4/word.
__device__ unsigned int g_gate[NQ];   // 4 MB static scratch

// ---------------------------------------------------------------------------
// Kernel 1: gate kernel with in-CTA spike pack + active-plane skipping.
//   One CTA per e-row (512 quads); each thread handles 2 quads.
//   Only delay planes with >=1 spike (any batch) are read (~2.7/8 planes),
//   cutting delaymap traffic 134 MB -> ~45 MB. One-hot => gate byte = m8(d).
// ---------------------------------------------------------------------------
__global__ void __launch_bounds__(256)
gate_kernel(const float4* __restrict__ dm4, const float* __restrict__ Xd) {
    const int e  = blockIdx.x;                        // one e per CTA
    const int i0 = e * 512 + threadIdx.x;             // first quad
    const int i1 = i0 + 256;                          // second quad

    __shared__ unsigned sm_bits[2];
    if (threadIdx.x < 64) {
        const bool sp = Xd[(size_t)threadIdx.x * NN + e] > 0.5f;
        const unsigned bal = __ballot_sync(0xFFFFFFFFu, sp);
        if ((threadIdx.x & 31) == 0) sm_bits[threadIdx.x >> 5] = bal;
    }
    __syncthreads();
    const unsigned long long bits =
        (unsigned long long)sm_bits[0] | ((unsigned long long)sm_bits[1] << 32);

    unsigned a0 = 0, a1 = 0, a2 = 0, a3 = 0;   // gate bytes, quad 0
    unsigned b0 = 0, b1 = 0, b2 = 0, b3 = 0;   // gate bytes, quad 1
#pragma unroll
    for (int d = 0; d < DD; d++) {
        const unsigned m8 = (unsigned)(bits >> (d * 8)) & 0xFFu;
        if (m8) {                                     // CTA-uniform branch
            const float4 u = dm4[(size_t)d * NQ + i0];
            const float4 v = dm4[(size_t)d * NQ + i1];
            if (u.x > 0.5f) a0 = m8;
            if (u.y > 0.5f) a1 = m8;
            if (u.z > 0.5f) a2 = m8;
            if (u.w > 0.5f) a3 = m8;
            if (v.x > 0.5f) b0 = m8;
            if (v.y > 0.5f) b1 = m8;
            if (v.z > 0.5f) b2 = m8;
            if (v.w > 0.5f) b3 = m8;
        }
    }
    g_gate[i0] = a0 | (a1 << 8) | (a2 << 16) | (a3 << 24);
    g_gate[i1] = b0 | (b1 << 8) | (b2 << 16) | (b3 << 24);
}

// ---------------------------------------------------------------------------
// Kernel 2: gated blend + reduce over 32e x 32o tiles.
//   Phase A: cooperative coalesced prefetch of gates (1 KB) + statics (12 KB)
//            into smem (float4 streams, deep MLP).
//   Phase B: warp b iterates 32 e's over its 32 o's; per iteration only
//            3 conflict-free LDS + 1 predicated Wlong LDG (the sole DRAM
//            access). Predicate comes from smem -> LDGs batch across the
//            unrolled loop; acc is FMA-only.
// ---------------------------------------------------------------------------
#define ET 32   // e-tile
#define OT 32   // o-tile

__global__ void __launch_bounds__(256)
reduce_kernel(const float4* __restrict__ W4,    // (N,N)
              const float*  __restrict__ Wl,    // Wlong (B,N,N)
              const float4* __restrict__ F4,    // STDP_frac (N,N)
              const float4* __restrict__ S4,    // signs (N,N)
              float* __restrict__ out)          // (B,N)
{
    __shared__ float    sS[ET][OT];
    __shared__ float    sW[ET][OT];
    __shared__ float    sF[ET][OT];
    __shared__ unsigned sG[ET][OT + 1];   // +1 pad: conflict-free column reads

    const int obase = blockIdx.x * OT;
    const int ebase = blockIdx.y * ET;
    const int t     = threadIdx.x;

    // ---- Phase A: prefetch tile ----
    {   // statics: 1024 floats per array = 256 float4; thread t -> row t/8, quad t%8
        const int ee = t >> 3;
        const int qq = t & 7;
        const size_t g4 = ((size_t)(ebase + ee) * NN + obase) / 4 + qq;
        *(float4*)&sS[ee][qq * 4] = S4[g4];
        *(float4*)&sW[ee][qq * 4] = W4[g4];
        *(float4*)&sF[ee][qq * 4] = F4[g4];
        // gates: one packed uint (4 o's) per thread, expand to bytes
        const unsigned gp = g_gate[(size_t)(ebase + ee) * (NN / 4) + obase / 4 + qq];
        sG[ee][qq * 4 + 0] = gp         & 0xFFu;
        sG[ee][qq * 4 + 1] = (gp >> 8)  & 0xFFu;
        sG[ee][qq * 4 + 2] = (gp >> 16) & 0xFFu;
        sG[ee][qq * 4 + 3] = (gp >> 24) & 0xFFu;
    }
    __syncthreads();

    // ---- Phase B: per-warp batch reduction ----
    const int lane = t & 31;
    const int b    = t >> 5;                         // warp index = batch
    const float* __restrict__ wlp =
        Wl + (size_t)b * NN2 + (size_t)ebase * NN + obase + lane;

    float acc = 0.0f;
#pragma unroll 8
    for (int ee = 0; ee < ET; ee++) {
        const unsigned g = sG[ee][lane];
        const bool on = (g >> b) & 1u;
        const float s = sS[ee][lane];
        const float w = sW[ee][lane];
        const float f = sF[ee][lane];
        float wl = 0.0f;
        if (on) wl = wlp[(size_t)ee * NN];           // @P LDG: only DRAM access
        if (on) acc += s * fmaf(f, wl - w, w);       // s*(w*(1-f)+wl*f)
    }

    atomicAdd(&out[b * NN + obase + lane], acc);
}

// ---------------------------------------------------------------------------
// Launch
// ---------------------------------------------------------------------------
extern "C" void kernel_launch(void* const* d_in, const int* in_sizes, int n_in,
                              void* d_out, int out_size) {
    const float* Xd = (const float*)d_in[0];   // (D,B,N)
    const float* dm = (const float*)d_in[1];   // (D,N,N)
    const float* W  = (const float*)d_in[2];   // (N,N)
    const float* Wl = (const float*)d_in[3];   // (B,N,N)
    const float* F  = (const float*)d_in[4];   // (N,N)
    const float* S  = (const float*)d_in[5];   // (N,N)
    float* out = (float*)d_out;                // (B,N)

    cudaMemsetAsync(out, 0, BB * NN * sizeof(float));

    gate_kernel<<<NN, 256>>>((const float4*)dm, Xd);

    dim3 grid(NN / OT, NN / ET);   // 64 x 64 = 4096 CTAs
    reduce_kernel<<<grid, 256>>>((const float4*)W, Wl,
                                 (const float4*)F, (const float4*)S, out);
}